// round 2
// baseline (speedup 1.0000x reference)
#include <cuda_runtime.h>

// Per-i losses + completion counter. __device__ globals are allocation-guard safe.
__device__ float g_loss[65536];
__device__ unsigned int g_count = 0;

__device__ __forceinline__ float warp_sum(float v) {
    #pragma unroll
    for (int off = 16; off > 0; off >>= 1)
        v += __shfl_down_sync(0xFFFFFFFFu, v, off);
    return v;
}

__global__ void __launch_bounds__(256)
triplet_fused_kernel(const float* __restrict__ feats,
                     const float* __restrict__ label,
                     const int*   __restrict__ idx1,
                     const int*   __restrict__ idx2,
                     float* __restrict__ out,
                     int B, int D) {
    const int i = blockIdx.x;

    // _fix_indices replication
    const int r1 = idx1[i];
    const int r2 = idx2[i];
    int a = (i + 1 + (r1 % (B - 1))) % B;
    int b = (i + 1 + (r2 % (B - 1))) % B;
    if (b == a) b = (i + 1 + ((r2 + 1) % (B - 1))) % B;

    const float4* __restrict__ A  = (const float4*)(feats + (size_t)i * D);
    const float4* __restrict__ T1 = (const float4*)(feats + (size_t)a * D);
    const float4* __restrict__ T2 = (const float4*)(feats + (size_t)b * D);

    const int n4 = D >> 2;
    float s1 = 0.f, s2 = 0.f;

    if (n4 == 512) {
        // D=2048 fast path: 2 iterations at 256 threads, all 6 loads front-batched.
        const int t = threadIdx.x;
        float4 a0 = A[t];
        float4 a1 = A[t + 256];
        float4 p0 = T1[t];
        float4 p1 = T1[t + 256];
        float4 q0 = T2[t];
        float4 q1 = T2[t + 256];
        float d;
        d = a0.x - p0.x; s1 = fmaf(d, d, s1);
        d = a0.y - p0.y; s1 = fmaf(d, d, s1);
        d = a0.z - p0.z; s1 = fmaf(d, d, s1);
        d = a0.w - p0.w; s1 = fmaf(d, d, s1);
        d = a1.x - p1.x; s1 = fmaf(d, d, s1);
        d = a1.y - p1.y; s1 = fmaf(d, d, s1);
        d = a1.z - p1.z; s1 = fmaf(d, d, s1);
        d = a1.w - p1.w; s1 = fmaf(d, d, s1);
        d = a0.x - q0.x; s2 = fmaf(d, d, s2);
        d = a0.y - q0.y; s2 = fmaf(d, d, s2);
        d = a0.z - q0.z; s2 = fmaf(d, d, s2);
        d = a0.w - q0.w; s2 = fmaf(d, d, s2);
        d = a1.x - q1.x; s2 = fmaf(d, d, s2);
        d = a1.y - q1.y; s2 = fmaf(d, d, s2);
        d = a1.z - q1.z; s2 = fmaf(d, d, s2);
        d = a1.w - q1.w; s2 = fmaf(d, d, s2);
    } else {
        for (int j = threadIdx.x; j < n4; j += blockDim.x) {
            float4 av = A[j];
            float4 v1 = T1[j];
            float4 v2 = T2[j];
            float d;
            d = av.x - v1.x; s1 = fmaf(d, d, s1);
            d = av.y - v1.y; s1 = fmaf(d, d, s1);
            d = av.z - v1.z; s1 = fmaf(d, d, s1);
            d = av.w - v1.w; s1 = fmaf(d, d, s1);
            d = av.x - v2.x; s2 = fmaf(d, d, s2);
            d = av.y - v2.y; s2 = fmaf(d, d, s2);
            d = av.z - v2.z; s2 = fmaf(d, d, s2);
            d = av.w - v2.w; s2 = fmaf(d, d, s2);
        }
    }

    // Block reduction (8 warps)
    __shared__ float sh1[8], sh2[8];
    __shared__ bool isLast;
    s1 = warp_sum(s1);
    s2 = warp_sum(s2);
    const int lane = threadIdx.x & 31;
    const int wid  = threadIdx.x >> 5;
    if (lane == 0) { sh1[wid] = s1; sh2[wid] = s2; }
    __syncthreads();

    if (threadIdx.x == 0) {
        float t1s = 0.f, t2s = 0.f;
        #pragma unroll
        for (int w = 0; w < 8; w++) { t1s += sh1[w]; t2s += sh2[w]; }

        const float mu    = (float)136.72353790613718;
        const float sigma = (float)62.34640414043511;

        float li_raw = label[i];
        float la = label[a]; if (a < i) la = (la - mu) / sigma;  // normalized by earlier step a
        float lb = label[b]; if (b < i) lb = (lb - mu) / sigma;

        float ld1 = fabsf(li_raw - la);
        float ld2 = fabsf(li_raw - lb);
        bool cond = (ld1 >= ld2);

        float dp = cond ? t2s : t1s;   // anchor->near squared distance
        float dn = cond ? t1s : t2s;   // anchor->far  squared distance
        float near_l = cond ? lb : la;
        float far_l  = cond ? la : lb;

        float li = (li_raw - mu) / sigma;
        float nl = (near_l - mu) / sigma;  // may be double-normalized — matches reference
        float fl = (far_l  - mu) / sigma;

        float alpha = (li - fl) * (li - fl) - (li - nl) * (li - nl);
        float loss  = dp - dn + 0.5f * alpha;
        g_loss[i] = loss > 0.f ? loss : 0.f;

        // Publish and count completion.
        __threadfence();
        unsigned int old = atomicAdd(&g_count, 1u);
        isLast = (old == (unsigned int)gridDim.x - 1u);
    }
    __syncthreads();

    if (isLast) {
        // Final deterministic reduction by the last block. g_loss is L2-hot.
        float s = 0.f;
        if ((B & 3) == 0) {
            const float4* gl = (const float4*)g_loss;
            const int nB4 = B >> 2;                 // 4096 for B=16384
            for (int j = threadIdx.x; j < nB4; j += 256) {
                float4 v = gl[j];
                s += (v.x + v.y) + (v.z + v.w);
            }
        } else {
            for (int j = threadIdx.x; j < B; j += 256)
                s += g_loss[j];
        }
        __shared__ float shf[256];
        shf[threadIdx.x] = s;
        __syncthreads();
        #pragma unroll
        for (int k = 128; k > 0; k >>= 1) {
            if (threadIdx.x < k) shf[threadIdx.x] += shf[threadIdx.x + k];
            __syncthreads();
        }
        if (threadIdx.x == 0) {
            out[0] = shf[0];
            g_count = 0;  // reset for next graph replay
        }
    }
}

extern "C" void kernel_launch(void* const* d_in, const int* in_sizes, int n_in,
                              void* d_out, int out_size) {
    const float* feats = (const float*)d_in[0];
    const float* label = (const float*)d_in[1];
    const int*   idx1  = (const int*)d_in[2];
    const int*   idx2  = (const int*)d_in[3];

    const int B = in_sizes[1];
    const int D = in_sizes[0] / B;

    triplet_fused_kernel<<<B, 256>>>(feats, label, idx1, idx2, (float*)d_out, B, D);
}

// round 3
// speedup vs baseline: 1.2939x; 1.2939x over previous
#include <cuda_runtime.h>

// Per-i losses. B=16384 for this problem; sized with headroom.
__device__ float g_loss[65536];

__device__ __forceinline__ float warp_sum(float v) {
    #pragma unroll
    for (int off = 16; off > 0; off >>= 1)
        v += __shfl_down_sync(0xFFFFFFFFu, v, off);
    return v;
}

__global__ void __launch_bounds__(256)
triplet_kernel(const float* __restrict__ feats,
               const float* __restrict__ label,
               const int*   __restrict__ idx1,
               const int*   __restrict__ idx2,
               int B, int D) {
    const int i = blockIdx.x;

    // _fix_indices replication
    const int r1 = idx1[i];
    const int r2 = idx2[i];
    int a = (i + 1 + (r1 % (B - 1))) % B;
    int b = (i + 1 + (r2 % (B - 1))) % B;
    if (b == a) b = (i + 1 + ((r2 + 1) % (B - 1))) % B;

    const float4* __restrict__ A  = (const float4*)(feats + (size_t)i * D);
    const float4* __restrict__ T1 = (const float4*)(feats + (size_t)a * D);
    const float4* __restrict__ T2 = (const float4*)(feats + (size_t)b * D);

    const int n4 = D >> 2;  // 512 for D=2048
    float s1 = 0.f, s2 = 0.f;
    for (int j = threadIdx.x; j < n4; j += blockDim.x) {
        float4 av = A[j];
        float4 v1 = T1[j];
        float4 v2 = T2[j];
        float d;
        d = av.x - v1.x; s1 = fmaf(d, d, s1);
        d = av.y - v1.y; s1 = fmaf(d, d, s1);
        d = av.z - v1.z; s1 = fmaf(d, d, s1);
        d = av.w - v1.w; s1 = fmaf(d, d, s1);
        d = av.x - v2.x; s2 = fmaf(d, d, s2);
        d = av.y - v2.y; s2 = fmaf(d, d, s2);
        d = av.z - v2.z; s2 = fmaf(d, d, s2);
        d = av.w - v2.w; s2 = fmaf(d, d, s2);
    }

    // Block reduction (8 warps)
    __shared__ float sh1[8], sh2[8];
    s1 = warp_sum(s1);
    s2 = warp_sum(s2);
    const int lane = threadIdx.x & 31;
    const int wid  = threadIdx.x >> 5;
    if (lane == 0) { sh1[wid] = s1; sh2[wid] = s2; }
    __syncthreads();

    if (threadIdx.x == 0) {
        float t1s = 0.f, t2s = 0.f;
        #pragma unroll
        for (int w = 0; w < 8; w++) { t1s += sh1[w]; t2s += sh2[w]; }

        const float mu    = (float)136.72353790613718;
        const float sigma = (float)62.34640414043511;

        float li_raw = label[i];
        float la = label[a]; if (a < i) la = (la - mu) / sigma;  // normalized by earlier step a
        float lb = label[b]; if (b < i) lb = (lb - mu) / sigma;

        float ld1 = fabsf(li_raw - la);
        float ld2 = fabsf(li_raw - lb);
        bool cond = (ld1 >= ld2);

        float dp = cond ? t2s : t1s;   // anchor->near squared distance
        float dn = cond ? t1s : t2s;   // anchor->far  squared distance
        float near_l = cond ? lb : la;
        float far_l  = cond ? la : lb;

        float li = (li_raw - mu) / sigma;
        float nl = (near_l - mu) / sigma;  // may be double-normalized — matches reference
        float fl = (far_l  - mu) / sigma;

        float alpha = (li - fl) * (li - fl) - (li - nl) * (li - nl);
        float loss  = dp - dn + 0.5f * alpha;
        g_loss[i] = loss > 0.f ? loss : 0.f;
    }
}

// Deterministic fixed-order reduction: 1024 threads, 4 float4 per thread,
// all loads front-batched for deep MLP. B=16384 -> 4096 float4 / 1024 = 4.
__global__ void __launch_bounds__(1024)
reduce_kernel(float* __restrict__ out, int B) {
    __shared__ float sh[32];
    const int t = threadIdx.x;
    float s = 0.f;

    if (B == 16384) {
        const float4* __restrict__ gl = (const float4*)g_loss;
        float4 v0 = gl[t];
        float4 v1 = gl[t + 1024];
        float4 v2 = gl[t + 2048];
        float4 v3 = gl[t + 3072];
        s = ((v0.x + v0.y) + (v0.z + v0.w))
          + ((v1.x + v1.y) + (v1.z + v1.w))
          + ((v2.x + v2.y) + (v2.z + v2.w))
          + ((v3.x + v3.y) + (v3.z + v3.w));
    } else {
        for (int j = t; j < B; j += 1024)
            s += g_loss[j];
    }

    s = warp_sum(s);
    const int lane = t & 31;
    const int wid  = t >> 5;
    if (lane == 0) sh[wid] = s;
    __syncthreads();
    if (wid == 0) {
        float v = (lane < 32) ? sh[lane] : 0.f;
        v = warp_sum(v);
        if (lane == 0) out[0] = v;
    }
}

extern "C" void kernel_launch(void* const* d_in, const int* in_sizes, int n_in,
                              void* d_out, int out_size) {
    const float* feats = (const float*)d_in[0];
    const float* label = (const float*)d_in[1];
    const int*   idx1  = (const int*)d_in[2];
    const int*   idx2  = (const int*)d_in[3];

    const int B = in_sizes[1];
    const int D = in_sizes[0] / B;

    triplet_kernel<<<B, 256>>>(feats, label, idx1, idx2, B, D);
    reduce_kernel<<<1, 1024>>>((float*)d_out, B);
}

// round 4
// speedup vs baseline: 1.6077x; 1.2425x over previous
#include <cuda_runtime.h>

// Per-CTA partial sums (8 warp-losses each). 16384/8 = 2048 for this problem.
__device__ float g_block[16384];

__device__ __forceinline__ float warp_sum(float v) {
    #pragma unroll
    for (int off = 16; off > 0; off >>= 1)
        v += __shfl_down_sync(0xFFFFFFFFu, v, off);
    return v;
}

// One warp per i. 8 warps per CTA. Each warp computes loss_i (post-relu),
// the CTA sums its 8 losses into g_block[blockIdx.x].
__global__ void __launch_bounds__(256)
triplet_kernel(const float* __restrict__ feats,
               const float* __restrict__ label,
               const int*   __restrict__ idx1,
               const int*   __restrict__ idx2,
               int B, int D) {
    const int lane = threadIdx.x & 31;
    const int wid  = threadIdx.x >> 5;
    const int i    = blockIdx.x * 8 + wid;

    __shared__ float wloss[8];
    float loss = 0.f;

    if (i < B) {
        // _fix_indices replication (all lanes; broadcast loads of same address)
        const int r1 = idx1[i];
        const int r2 = idx2[i];
        int a = (i + 1 + (r1 % (B - 1))) % B;
        int b = (i + 1 + (r2 % (B - 1))) % B;
        if (b == a) b = (i + 1 + ((r2 + 1) % (B - 1))) % B;

        const float4* __restrict__ A  = (const float4*)(feats + (size_t)i * D);
        const float4* __restrict__ T1 = (const float4*)(feats + (size_t)a * D);
        const float4* __restrict__ T2 = (const float4*)(feats + (size_t)b * D);

        const int n4 = D >> 2;   // 512 for D=2048
        float s1 = 0.f, s2 = 0.f;

        if ((n4 & 127) == 0) {
            // Fast path: n4 multiple of 128 -> chunks of 4 j-steps per warp.
            const int nchunk = n4 >> 7;          // 4 for D=2048
            for (int c = 0; c < nchunk; ++c) {
                const int base = lane + c * 128;
                float4 av[4], v1[4], v2[4];
                // 12 front-batched float4 loads per thread
                #pragma unroll
                for (int u = 0; u < 4; ++u) av[u] = A[base + u * 32];
                #pragma unroll
                for (int u = 0; u < 4; ++u) v1[u] = T1[base + u * 32];
                #pragma unroll
                for (int u = 0; u < 4; ++u) v2[u] = T2[base + u * 32];
                #pragma unroll
                for (int u = 0; u < 4; ++u) {
                    float d;
                    d = av[u].x - v1[u].x; s1 = fmaf(d, d, s1);
                    d = av[u].y - v1[u].y; s1 = fmaf(d, d, s1);
                    d = av[u].z - v1[u].z; s1 = fmaf(d, d, s1);
                    d = av[u].w - v1[u].w; s1 = fmaf(d, d, s1);
                    d = av[u].x - v2[u].x; s2 = fmaf(d, d, s2);
                    d = av[u].y - v2[u].y; s2 = fmaf(d, d, s2);
                    d = av[u].z - v2[u].z; s2 = fmaf(d, d, s2);
                    d = av[u].w - v2[u].w; s2 = fmaf(d, d, s2);
                }
            }
        } else {
            for (int j = lane; j < n4; j += 32) {
                float4 av = A[j];
                float4 v1 = T1[j];
                float4 v2 = T2[j];
                float d;
                d = av.x - v1.x; s1 = fmaf(d, d, s1);
                d = av.y - v1.y; s1 = fmaf(d, d, s1);
                d = av.z - v1.z; s1 = fmaf(d, d, s1);
                d = av.w - v1.w; s1 = fmaf(d, d, s1);
                d = av.x - v2.x; s2 = fmaf(d, d, s2);
                d = av.y - v2.y; s2 = fmaf(d, d, s2);
                d = av.z - v2.z; s2 = fmaf(d, d, s2);
                d = av.w - v2.w; s2 = fmaf(d, d, s2);
            }
        }

        s1 = warp_sum(s1);
        s2 = warp_sum(s2);

        if (lane == 0) {
            const float mu    = (float)136.72353790613718;
            const float sigma = (float)62.34640414043511;

            float li_raw = label[i];
            float la = label[a]; if (a < i) la = (la - mu) / sigma;  // normalized by earlier step
            float lb = label[b]; if (b < i) lb = (lb - mu) / sigma;

            float ld1 = fabsf(li_raw - la);
            float ld2 = fabsf(li_raw - lb);
            bool cond = (ld1 >= ld2);

            float dp = cond ? s2 : s1;    // anchor->near squared distance
            float dn = cond ? s1 : s2;    // anchor->far  squared distance
            float near_l = cond ? lb : la;
            float far_l  = cond ? la : lb;

            float li = (li_raw - mu) / sigma;
            float nl = (near_l - mu) / sigma;  // may be double-normalized — matches reference
            float fl = (far_l  - mu) / sigma;

            float alpha = (li - fl) * (li - fl) - (li - nl) * (li - nl);
            float l = dp - dn + 0.5f * alpha;
            loss = l > 0.f ? l : 0.f;
        }
    }

    if (lane == 0) wloss[wid] = loss;
    __syncthreads();
    if (threadIdx.x == 0) {
        float s = 0.f;
        #pragma unroll
        for (int w = 0; w < 8; w++) s += wloss[w];
        g_block[blockIdx.x] = s;
    }
}

// Deterministic fixed-order reduction of the per-CTA partials.
__global__ void __launch_bounds__(512)
reduce_kernel(float* __restrict__ out, int nblocks) {
    __shared__ float sh[16];
    const int t = threadIdx.x;
    float s = 0.f;

    if (nblocks == 2048) {
        const float4* __restrict__ gb = (const float4*)g_block;
        float4 v = gb[t];                 // 512 threads x 1 float4 = 2048 floats
        s = (v.x + v.y) + (v.z + v.w);
    } else {
        for (int j = t; j < nblocks; j += 512)
            s += g_block[j];
    }

    s = warp_sum(s);
    const int lane = t & 31;
    const int wid  = t >> 5;
    if (lane == 0) sh[wid] = s;
    __syncthreads();
    if (wid == 0) {
        float v = (lane < 16) ? sh[lane] : 0.f;
        v = warp_sum(v);
        if (lane == 0) out[0] = v;
    }
}

extern "C" void kernel_launch(void* const* d_in, const int* in_sizes, int n_in,
                              void* d_out, int out_size) {
    const float* feats = (const float*)d_in[0];
    const float* label = (const float*)d_in[1];
    const int*   idx1  = (const int*)d_in[2];
    const int*   idx2  = (const int*)d_in[3];

    const int B = in_sizes[1];
    const int D = in_sizes[0] / B;
    const int nblocks = (B + 7) / 8;

    triplet_kernel<<<nblocks, 256>>>(feats, label, idx1, idx2, B, D);
    reduce_kernel<<<1, 512>>>((float*)d_out, nblocks);
}